// round 15
// baseline (speedup 1.0000x reference)
#include <cuda_runtime.h>
#include <cuda_fp16.h>
#include <cstdint>

// ---------------------------------------------------------------------------
// Problem constants
// ---------------------------------------------------------------------------
#define BATCH 8
#define NTOK  4096          // 64*64 tokens per batch
#define CDIM  256
#define NQKV  320           // 32 q | 32 k | 256 v
#define NROWS (BATCH * NTOK)   // 32768

// ---------------------------------------------------------------------------
// Device scratch
// ---------------------------------------------------------------------------
__device__ float g_ball[NQKV];

__device__ __align__(16) __half g_Wth[NQKV * CDIM];    // W^T hi [n][k]
__device__ __align__(16) __half g_Wtl[NQKV * CDIM];    // W^T lo [n][k]
__device__ __align__(16) __half g_x16h[(size_t)NROWS * CDIM]; // x hi
__device__ __align__(16) __half g_x16l[(size_t)NROWS * CDIM]; // x lo

__device__ __align__(16) __half g_q16[(size_t)NROWS * 64];   // [tok][qh32|ql32]
__device__ __align__(16) __half g_k16[(size_t)NROWS * 64];   // [tok][kh32|kl32]
__device__ __align__(16) __half g_v16[(size_t)NROWS * CDIM]; // fp16 v [tok][c]
__device__ __align__(16) __half g_vt[(size_t)BATCH * CDIM * NTOK]; // [b][c][n] fp16

// ---------------------------------------------------------------------------
// Helpers (baseline-ISA only: mma.sync / ldmatrix / cp.async)
// ---------------------------------------------------------------------------
__device__ __forceinline__ uint32_t smem_to_u32(const void* p) {
    uint32_t a;
    asm("{ .reg .u64 t; cvta.to.shared.u64 t, %1; cvt.u32.u64 %0, t; }" : "=r"(a) : "l"(p));
    return a;
}

__device__ __forceinline__ void ldsm4(uint32_t& r0, uint32_t& r1, uint32_t& r2, uint32_t& r3,
                                      uint32_t addr) {
    asm volatile("ldmatrix.sync.aligned.m8n8.x4.shared.b16 {%0,%1,%2,%3}, [%4];"
                 : "=r"(r0), "=r"(r1), "=r"(r2), "=r"(r3) : "r"(addr));
}

__device__ __forceinline__ void mma_f16(float c[4], uint32_t a0, uint32_t a1, uint32_t a2,
                                        uint32_t a3, uint32_t b0, uint32_t b1) {
    asm volatile(
        "mma.sync.aligned.m16n8k16.row.col.f32.f16.f16.f32 "
        "{%0,%1,%2,%3}, {%4,%5,%6,%7}, {%8,%9}, {%0,%1,%2,%3};"
        : "+f"(c[0]), "+f"(c[1]), "+f"(c[2]), "+f"(c[3])
        : "r"(a0), "r"(a1), "r"(a2), "r"(a3), "r"(b0), "r"(b1));
}

__device__ __forceinline__ uint32_t pack_h2(float lo, float hi) {
    __half2 h = __floats2half2_rn(lo, hi);
    return *reinterpret_cast<uint32_t*>(&h);
}

#define CP_ASYNC16(dst_u32, src_ptr) \
    asm volatile("cp.async.cg.shared.global [%0], [%1], 16;" \
                 :: "r"(dst_u32), "l"(src_ptr) : "memory")
#define CP_COMMIT()  asm volatile("cp.async.commit_group;" ::: "memory")
#define CP_WAIT1()   asm volatile("cp.async.wait_group 1;" ::: "memory")
#define CP_WAIT0()   asm volatile("cp.async.wait_group 0;" ::: "memory")

// ---------------------------------------------------------------------------
// Kernel 1: prep = pack weights (split W^T hi/lo + bias) + split x hi/lo
// ---------------------------------------------------------------------------
#define PACKB ((NQKV * CDIM + 255) / 256)              // 320
#define XB    ((int)((size_t)NROWS * CDIM / 4 / 256))  // 8192

__global__ void prep(const float* __restrict__ x,
                     const float* __restrict__ Wq, const float* __restrict__ Wk,
                     const float* __restrict__ Wv, const float* __restrict__ bq,
                     const float* __restrict__ bk, const float* __restrict__ bv) {
    if (blockIdx.x < PACKB) {
        int i = blockIdx.x * blockDim.x + threadIdx.x;
        if (i < NQKV * CDIM) {
            int n = i >> 8, k = i & 255;
            float w;
            if (n < 32)       w = Wq[k * 32 + n];
            else if (n < 64)  w = Wk[k * 32 + (n - 32)];
            else              w = Wv[k * 256 + (n - 64)];
            __half wh = __float2half_rn(w);
            g_Wth[i] = wh;
            g_Wtl[i] = __float2half_rn(w - __half2float(wh));
        }
        if (i < NQKV)
            g_ball[i] = (i < 32) ? bq[i] : (i < 64 ? bk[i - 32] : bv[i - 64]);
    } else {
        int i = (blockIdx.x - PACKB) * blockDim.x + threadIdx.x;
        if (i >= (int)((size_t)NROWS * CDIM / 4)) return;
        float4 v = ((const float4*)x)[i];
        __half hx = __float2half_rn(v.x), hy = __float2half_rn(v.y);
        __half hz = __float2half_rn(v.z), hw = __float2half_rn(v.w);
        __half2 h01 = __halves2half2(hx, hy);
        __half2 h23 = __halves2half2(hz, hw);
        __half2 l01 = __floats2half2_rn(v.x - __half2float(hx), v.y - __half2float(hy));
        __half2 l23 = __floats2half2_rn(v.z - __half2float(hz), v.w - __half2float(hw));
        ((uint2*)g_x16h)[i] = make_uint2(*(uint32_t*)&h01, *(uint32_t*)&h23);
        ((uint2*)g_x16l)[i] = make_uint2(*(uint32_t*)&l01, *(uint32_t*)&l23);
    }
}

// ---------------------------------------------------------------------------
// Kernel 2: split-fp16 tensor-core GEMM  qkv = x @ W + b
// BM=128, BN=64, K-chunk 32, 256 threads / 8 warps.
// Epilogue: bn0==0 -> q/k written as split fp16; else v written fp16 [tok][c].
// ---------------------------------------------------------------------------
#define GSTRIDE 80
#define GS_AH   0
#define GS_AL   10240
#define GS_BH   20480
#define GS_BL   25600
#define G_STAGE 30720
#define G_SMEM  (2 * G_STAGE)             // 61440

__global__ __launch_bounds__(256) void qkv_gemm_f16() {
    extern __shared__ char gsm[];
    const uint32_t sb = smem_to_u32(gsm);
    const int tid = threadIdx.x, wid = tid >> 5, lane = tid & 31;
    const int bn0 = blockIdx.x * 64;
    const int bm0 = blockIdx.y * 128;
    const int m0 = wid * 16;

    const __half* xh = g_x16h + (size_t)bm0 * CDIM;
    const __half* xl = g_x16l + (size_t)bm0 * CDIM;
    const __half* wth = g_Wth + (size_t)bn0 * CDIM;
    const __half* wtl = g_Wtl + (size_t)bn0 * CDIM;

    {
        const uint32_t S = sb;
#pragma unroll
        for (int t = 0; t < 2; t++) {
            int id = t * 256 + tid; int row = id >> 2, seg = id & 3;
            CP_ASYNC16(S + GS_AH + row * GSTRIDE + seg * 16, xh + (size_t)row * CDIM + seg * 8);
            CP_ASYNC16(S + GS_AL + row * GSTRIDE + seg * 16, xl + (size_t)row * CDIM + seg * 8);
        }
        {
            int row = tid >> 2, seg = tid & 3;
            CP_ASYNC16(S + GS_BH + row * GSTRIDE + seg * 16, wth + (size_t)row * CDIM + seg * 8);
            CP_ASYNC16(S + GS_BL + row * GSTRIDE + seg * 16, wtl + (size_t)row * CDIM + seg * 8);
        }
        CP_COMMIT();
    }

    float D[8][4];
#pragma unroll
    for (int j = 0; j < 8; j++) { D[j][0] = D[j][1] = D[j][2] = D[j][3] = 0.0f; }

    const int g = lane >> 3;
    const uint32_t aOff = (uint32_t)(m0 + ((g & 1) << 3) + (lane & 7)) * GSTRIDE + ((g >> 1) << 4);
    const uint32_t bOff = (uint32_t)(lane & 7) * GSTRIDE + ((lane >> 3) << 4);

    int buf = 0;
    for (int kt = 0; kt < 8; kt++) {
        if (kt < 7) {
            const int k0n = (kt + 1) * 32;
            const uint32_t S = sb + (buf ^ 1) * G_STAGE;
#pragma unroll
            for (int t = 0; t < 2; t++) {
                int id = t * 256 + tid; int row = id >> 2, seg = id & 3;
                CP_ASYNC16(S + GS_AH + row * GSTRIDE + seg * 16,
                           xh + (size_t)row * CDIM + k0n + seg * 8);
                CP_ASYNC16(S + GS_AL + row * GSTRIDE + seg * 16,
                           xl + (size_t)row * CDIM + k0n + seg * 8);
            }
            {
                int row = tid >> 2, seg = tid & 3;
                CP_ASYNC16(S + GS_BH + row * GSTRIDE + seg * 16,
                           wth + (size_t)row * CDIM + k0n + seg * 8);
                CP_ASYNC16(S + GS_BL + row * GSTRIDE + seg * 16,
                           wtl + (size_t)row * CDIM + k0n + seg * 8);
            }
            CP_COMMIT();
            CP_WAIT1();
        } else {
            CP_WAIT0();
        }
        __syncthreads();

        const uint32_t S = sb + buf * G_STAGE;
        uint32_t ah[2][4], al[2][4];
        ldsm4(ah[0][0], ah[0][1], ah[0][2], ah[0][3], S + GS_AH + aOff);
        ldsm4(ah[1][0], ah[1][1], ah[1][2], ah[1][3], S + GS_AH + aOff + 32);
        ldsm4(al[0][0], al[0][1], al[0][2], al[0][3], S + GS_AL + aOff);
        ldsm4(al[1][0], al[1][1], al[1][2], al[1][3], S + GS_AL + aOff + 32);

#pragma unroll
        for (int n8 = 0; n8 < 8; n8++) {
            uint32_t bh0, bh1, bh2, bh3, bl0, bl1, bl2, bl3;
            ldsm4(bh0, bh1, bh2, bh3, S + GS_BH + (uint32_t)(n8 * 8) * GSTRIDE + bOff);
            ldsm4(bl0, bl1, bl2, bl3, S + GS_BL + (uint32_t)(n8 * 8) * GSTRIDE + bOff);
            mma_f16(D[n8], ah[0][0], ah[0][1], ah[0][2], ah[0][3], bh0, bh1);
            mma_f16(D[n8], ah[1][0], ah[1][1], ah[1][2], ah[1][3], bh2, bh3);
            mma_f16(D[n8], ah[0][0], ah[0][1], ah[0][2], ah[0][3], bl0, bl1);
            mma_f16(D[n8], ah[1][0], ah[1][1], ah[1][2], ah[1][3], bl2, bl3);
            mma_f16(D[n8], al[0][0], al[0][1], al[0][2], al[0][3], bh0, bh1);
            mma_f16(D[n8], al[1][0], al[1][1], al[1][2], al[1][3], bh2, bh3);
        }
        __syncthreads();
        buf ^= 1;
    }

    // epilogue
    const int r = bm0 + m0 + (lane >> 2);
    if (bn0 == 0) {
        // q/k: split to fp16 hi/lo, layout [tok][hi32|lo32]
#pragma unroll
        for (int n8 = 0; n8 < 8; n8++) {
            const int col = n8 * 8 + ((lane & 3) << 1);     // 0..62 even
            float b0 = g_ball[col], b1 = g_ball[col + 1];
            __half* dst = (col < 32) ? g_q16 : g_k16;
            const int c = col & 31;
#pragma unroll
            for (int h = 0; h < 2; h++) {
                const int rr = r + h * 8;
                float v0 = D[n8][h * 2 + 0] + b0;
                float v1 = D[n8][h * 2 + 1] + b1;
                __half h0 = __float2half_rn(v0);
                __half h1 = __float2half_rn(v1);
                __half2 hh = __halves2half2(h0, h1);
                *(uint32_t*)&dst[(size_t)rr * 64 + c] = *(uint32_t*)&hh;
                *(uint32_t*)&dst[(size_t)rr * 64 + 32 + c] =
                    pack_h2(v0 - __half2float(h0), v1 - __half2float(h1));
            }
        }
    } else {
        // v: fp16 [tok][c]
#pragma unroll
        for (int n8 = 0; n8 < 8; n8++) {
            const int gc = bn0 + n8 * 8 + ((lane & 3) << 1);
            const int col = gc - 64;
            uint32_t o0 = pack_h2(D[n8][0] + g_ball[gc], D[n8][1] + g_ball[gc + 1]);
            uint32_t o1 = pack_h2(D[n8][2] + g_ball[gc], D[n8][3] + g_ball[gc + 1]);
            *(uint32_t*)&g_v16[(size_t)r * CDIM + col] = o0;
            *(uint32_t*)&g_v16[(size_t)(r + 8) * CDIM + col] = o1;
        }
    }
}

// ---------------------------------------------------------------------------
// Kernel 3: transpose V (fp16) to [b][c][n] fp16
// ---------------------------------------------------------------------------
__global__ void convert_v() {
    __shared__ float tile[32][33];
    const int b = blockIdx.z;
    const int n0 = blockIdx.x * 32, c0 = blockIdx.y * 32;
    const int tx = threadIdx.x, ty = threadIdx.y;   // 32 x 8
#pragma unroll
    for (int i = 0; i < 4; i++) {
        int n = n0 + ty + i * 8;
        tile[ty + i * 8][tx] =
            __half2float(g_v16[((size_t)(b * NTOK + n)) * CDIM + c0 + tx]);
    }
    __syncthreads();
#pragma unroll
    for (int i = 0; i < 4; i++) {
        int c = c0 + ty + i * 8;
        g_vt[((size_t)(b * CDIM + c)) * NTOK + n0 + tx] =
            __float2half_rn(tile[tx][ty + i * 8]);
    }
}

// ---------------------------------------------------------------------------
// Kernel 4: fp16 warp-mma flash attention, 64-query CTA, 2 CTAs/SM
// 256 threads / 8 warps; warp (rg 0..3, ch 0..1): rows rg*16..+15,
// channels ch*128..+127. Full-row 2-term QK duplicated per channel-half warp
// (softmax warp-local, no cross-warp exchange). R11 pipeline order.
// Two INDEPENDENT CTAs per SM decorrelate QK/softmax/PV phases.
// ---------------------------------------------------------------------------
#define QSTRIDE 144
#define KSTRIDE 80                          // 64B K-hi data + 16B pad
#define VSTRIDE 144                         // 128B V data + 16B pad
#define SM_Q    0                           // 64*144 = 9216
#define SM_K    9216                        // 2 * 5120
#define K_BUF   5120
#define SM_V    (9216 + 2 * 5120)           // 19456; 2 * 36864
#define V_BUF   36864
#define SM_TOTAL (19456 + 2 * 36864)        // 93184 bytes (x2 CTAs = 186368 <= 228KB)

__global__ __launch_bounds__(256, 2) void attn_mma(const float* __restrict__ x,
                                                   const float* __restrict__ gamma_p,
                                                   float* __restrict__ out) {
    extern __shared__ char sm[];
    const uint32_t sb = smem_to_u32(sm);
    const int tid = threadIdx.x, wid = tid >> 5, lane = tid & 31;
    const int rg = wid & 3, ch = wid >> 2;
    const int b = blockIdx.y;
    const int r0 = blockIdx.x * 64;
    const int m0 = rg * 16;

    const __half* qsrc = g_q16 + (size_t)(b * NTOK + r0) * 64;
    const __half* ksrc = g_k16 + (size_t)b * NTOK * 64;
    const __half* vsrc = g_vt + (size_t)b * CDIM * NTOK;

    // ---- load Q tile [64 rows][128B] ----
#pragma unroll
    for (int t = 0; t < 2; t++) {
        int id = t * 256 + tid;
        int row = id >> 3, c = id & 7;
        float4 v = *(const float4*)(qsrc + (size_t)row * 64 + c * 8);
        *(float4*)(sm + SM_Q + row * QSTRIDE + c * 16) = v;
    }

    // ---- prefetch tile 0 into stage 0 ----
    {   // K hi: 64 rows x 4 chunks = 256 cp
        int row = tid >> 2, seg = tid & 3;
        CP_ASYNC16(sb + SM_K + row * KSTRIDE + seg * 16, ksrc + (size_t)row * 64 + seg * 8);
    }
#pragma unroll
    for (int t = 0; t < 8; t++) {   // V: 256 rows x 8 chunks = 2048 cp
        int id = t * 256 + tid; int row = id >> 3, c = id & 7;
        CP_ASYNC16(sb + SM_V + row * VSTRIDE + c * 16, vsrc + (size_t)row * NTOK + c * 8);
    }
    CP_COMMIT();
    __syncthreads();   // Q visible for ldmatrix

    // ---- Q A-fragments (persistent): qa[0,1]=hi dims 0..31, qa[2,3]=lo ----
    uint32_t qa[4][4];
    {
        int g = lane >> 3;
        uint32_t base = sb + SM_Q + (uint32_t)(m0 + ((g & 1) << 3) + (lane & 7)) * QSTRIDE
                        + ((g >> 1) << 4);
#pragma unroll
        for (int kf = 0; kf < 4; kf++)
            ldsm4(qa[kf][0], qa[kf][1], qa[kf][2], qa[kf][3], base + kf * 32);
    }

    const uint32_t bOffK = (uint32_t)(lane & 7) * KSTRIDE + ((lane >> 3) << 4);
    const uint32_t bOffV = (uint32_t)(lane & 7) * VSTRIDE + ((lane >> 3) << 4);

    float D[16][4];
#pragma unroll
    for (int j = 0; j < 16; j++) { D[j][0] = D[j][1] = D[j][2] = D[j][3] = 0.0f; }
    float lsl = 0.0f, lsh = 0.0f;          // running full-row sums (thread-partial)
    float m_l = -1e30f, m_h = -1e30f;      // running full-row maxima

    int buf = 0;
    for (int jt = 0; jt < 64; jt++) {
        // prefetch tile jt+1 into buf^1 (safe: trailing sync of jt-1 passed)
        if (jt < 63) {
            const int j0n = (jt + 1) * 64;
            const int bn = buf ^ 1;
            {
                int row = tid >> 2, seg = tid & 3;
                CP_ASYNC16(sb + SM_K + bn * K_BUF + row * KSTRIDE + seg * 16,
                           ksrc + (size_t)(j0n + row) * 64 + seg * 8);
            }
#pragma unroll
            for (int t = 0; t < 8; t++) {
                int id = t * 256 + tid; int row = id >> 3, c = id & 7;
                CP_ASYNC16(sb + SM_V + bn * V_BUF + row * VSTRIDE + c * 16,
                           vsrc + (size_t)row * NTOK + j0n + c * 8);
            }
            CP_COMMIT();
            CP_WAIT1();
        } else {
            CP_WAIT0();
        }
        __syncthreads();

        const uint32_t Kb = sb + SM_K + buf * K_BUF;
        const uint32_t Vb = sb + SM_V + buf * V_BUF;

        // ---- full-row QK^T (2-term: S = (qh+ql)*kh), all 64 keys ----
        float S[8][4];
#pragma unroll
        for (int j = 0; j < 8; j++) { S[j][0] = S[j][1] = S[j][2] = S[j][3] = 0.0f; }
#pragma unroll
        for (int j = 0; j < 8; j++) {
            uint32_t kh0, kh1, kh2, kh3;
            ldsm4(kh0, kh1, kh2, kh3, Kb + (uint32_t)(j * 8) * KSTRIDE + bOffK);
            mma_f16(S[j], qa[0][0], qa[0][1], qa[0][2], qa[0][3], kh0, kh1);
            mma_f16(S[j], qa[1][0], qa[1][1], qa[1][2], qa[1][3], kh2, kh3);
            mma_f16(S[j], qa[2][0], qa[2][1], qa[2][2], qa[2][3], kh0, kh1);
            mma_f16(S[j], qa[3][0], qa[3][1], qa[3][2], qa[3][3], kh2, kh3);
        }

        // ---- online softmax (warp-local, full row) ----
        float mtl = -1e30f, mth = -1e30f;
#pragma unroll
        for (int j = 0; j < 8; j++) {
            mtl = fmaxf(mtl, fmaxf(S[j][0], S[j][1]));
            mth = fmaxf(mth, fmaxf(S[j][2], S[j][3]));
        }
        mtl = fmaxf(mtl, __shfl_xor_sync(0xffffffffu, mtl, 1));
        mtl = fmaxf(mtl, __shfl_xor_sync(0xffffffffu, mtl, 2));
        mth = fmaxf(mth, __shfl_xor_sync(0xffffffffu, mth, 1));
        mth = fmaxf(mth, __shfl_xor_sync(0xffffffffu, mth, 2));

        const float mnl = fmaxf(m_l, mtl);
        const float mnh = fmaxf(m_h, mth);
        const float al = __expf(m_l - mnl);
        const float ah = __expf(m_h - mnh);
        m_l = mnl; m_h = mnh;

        uint32_t pha[4][4];
        float psl = 0.0f, psh = 0.0f;
#pragma unroll
        for (int kf = 0; kf < 4; kf++) {
#pragma unroll
            for (int h = 0; h < 2; h++) {
                const int j = 2 * kf + h;
                float p0 = __expf(S[j][0] - mnl);
                float p1 = __expf(S[j][1] - mnl);
                float p2 = __expf(S[j][2] - mnh);
                float p3 = __expf(S[j][3] - mnh);
                psl += p0 + p1;
                psh += p2 + p3;
                pha[kf][h * 2 + 0] = pack_h2(p0, p1);   // row r
                pha[kf][h * 2 + 1] = pack_h2(p2, p3);   // row r+8
            }
        }
        lsl = lsl * al + psl;
        lsh = lsh * ah + psh;

        // rescale accumulators
#pragma unroll
        for (int j2 = 0; j2 < 16; j2++) {
            D[j2][0] *= al; D[j2][1] *= al;
            D[j2][2] *= ah; D[j2][3] *= ah;
        }

        // ---- PV over this warp's 128-channel half ----
#pragma unroll
        for (int j2 = 0; j2 < 16; j2++) {
            uint32_t v0, v1, v2, v3, v4, v5, v6, v7;
            uint32_t va = Vb + (uint32_t)(ch * 128 + j2 * 8) * VSTRIDE + bOffV;
            ldsm4(v0, v1, v2, v3, va);        // keys 0..31
            ldsm4(v4, v5, v6, v7, va + 64);   // keys 32..63
            mma_f16(D[j2], pha[0][0], pha[0][1], pha[0][2], pha[0][3], v0, v1);
            mma_f16(D[j2], pha[1][0], pha[1][1], pha[1][2], pha[1][3], v2, v3);
            mma_f16(D[j2], pha[2][0], pha[2][1], pha[2][2], pha[2][3], v4, v5);
            mma_f16(D[j2], pha[3][0], pha[3][1], pha[3][2], pha[3][3], v6, v7);
        }

        __syncthreads();   // all warps done with buf before next prefetch overwrites buf^1
        buf ^= 1;
    }

    // ---- row sums (quad reduction; warp-local full row) + epilogue ----
    lsl += __shfl_xor_sync(0xffffffffu, lsl, 1);
    lsl += __shfl_xor_sync(0xffffffffu, lsl, 2);
    lsh += __shfl_xor_sync(0xffffffffu, lsh, 1);
    lsh += __shfl_xor_sync(0xffffffffu, lsh, 2);

    const float g = *gamma_p;
    const float il = g / lsl;
    const float ih = g / lsh;
    const int r = r0 + m0 + (lane >> 2);
    const size_t base_lo = ((size_t)(b * NTOK) + r) * CDIM;
    const size_t base_hi = base_lo + 8 * CDIM;
#pragma unroll
    for (int j2 = 0; j2 < 16; j2++) {
        const int col = ch * 128 + j2 * 8 + ((lane & 3) << 1);
        float2 xv = *(const float2*)(x + base_lo + col);
        float2 o;
        o.x = D[j2][0] * il + xv.x;
        o.y = D[j2][1] * il + xv.y;
        *(float2*)(out + base_lo + col) = o;
        float2 xw = *(const float2*)(x + base_hi + col);
        float2 o2;
        o2.x = D[j2][2] * ih + xw.x;
        o2.y = D[j2][3] * ih + xw.y;
        *(float2*)(out + base_hi + col) = o2;
    }
}

// ---------------------------------------------------------------------------
extern "C" void kernel_launch(void* const* d_in, const int* in_sizes, int n_in,
                              void* d_out, int out_size) {
    const float* x     = (const float*)d_in[0];
    const float* Wq    = (const float*)d_in[1];
    const float* bq    = (const float*)d_in[2];
    const float* Wk    = (const float*)d_in[3];
    const float* bk    = (const float*)d_in[4];
    const float* Wv    = (const float*)d_in[5];
    const float* bv    = (const float*)d_in[6];
    const float* gamma = (const float*)d_in[7];
    float* out = (float*)d_out;

    prep<<<PACKB + XB, 256>>>(x, Wq, Wk, Wv, bq, bk, bv);

    cudaFuncSetAttribute(qkv_gemm_f16, cudaFuncAttributeMaxDynamicSharedMemorySize, G_SMEM);
    qkv_gemm_f16<<<dim3(NQKV / 64, NROWS / 128), 256, G_SMEM>>>();

    convert_v<<<dim3(NTOK / 32, CDIM / 32, BATCH), dim3(32, 8)>>>();

    cudaFuncSetAttribute(attn_mma, cudaFuncAttributeMaxDynamicSharedMemorySize, SM_TOTAL);
    attn_mma<<<dim3(NTOK / 64, BATCH), 256, SM_TOTAL>>>(x, gamma, out);
}

// round 16
// speedup vs baseline: 1.2337x; 1.2337x over previous
#include <cuda_runtime.h>
#include <cuda_fp16.h>
#include <cstdint>

// ---------------------------------------------------------------------------
// Problem constants
// ---------------------------------------------------------------------------
#define BATCH 8
#define NTOK  4096          // 64*64 tokens per batch
#define CDIM  256
#define NQKV  320           // 32 q | 32 k | 256 v
#define NROWS (BATCH * NTOK)   // 32768

// ---------------------------------------------------------------------------
// Device scratch
// ---------------------------------------------------------------------------
__device__ float g_ball[NQKV];

__device__ __align__(16) __half g_Wth[NQKV * CDIM];    // W^T hi [n][k]
__device__ __align__(16) __half g_Wtl[NQKV * CDIM];    // W^T lo [n][k]
__device__ __align__(16) __half g_x16h[(size_t)NROWS * CDIM]; // x hi
__device__ __align__(16) __half g_x16l[(size_t)NROWS * CDIM]; // x lo

__device__ __align__(16) __half g_q16[(size_t)NROWS * 64];   // [tok][qh32|ql32]
__device__ __align__(16) __half g_k16[(size_t)NROWS * 64];   // [tok][kh32|kl32]
__device__ __align__(16) __half g_v16[(size_t)NROWS * CDIM]; // fp16 v [tok][c]
__device__ __align__(16) __half g_vt[(size_t)BATCH * CDIM * NTOK]; // [b][c][n] fp16

// ---------------------------------------------------------------------------
// Helpers (baseline-ISA only: mma.sync / ldmatrix / cp.async)
// ---------------------------------------------------------------------------
__device__ __forceinline__ uint32_t smem_to_u32(const void* p) {
    uint32_t a;
    asm("{ .reg .u64 t; cvta.to.shared.u64 t, %1; cvt.u32.u64 %0, t; }" : "=r"(a) : "l"(p));
    return a;
}

__device__ __forceinline__ void ldsm4(uint32_t& r0, uint32_t& r1, uint32_t& r2, uint32_t& r3,
                                      uint32_t addr) {
    asm volatile("ldmatrix.sync.aligned.m8n8.x4.shared.b16 {%0,%1,%2,%3}, [%4];"
                 : "=r"(r0), "=r"(r1), "=r"(r2), "=r"(r3) : "r"(addr));
}

__device__ __forceinline__ void mma_f16(float c[4], uint32_t a0, uint32_t a1, uint32_t a2,
                                        uint32_t a3, uint32_t b0, uint32_t b1) {
    asm volatile(
        "mma.sync.aligned.m16n8k16.row.col.f32.f16.f16.f32 "
        "{%0,%1,%2,%3}, {%4,%5,%6,%7}, {%8,%9}, {%0,%1,%2,%3};"
        : "+f"(c[0]), "+f"(c[1]), "+f"(c[2]), "+f"(c[3])
        : "r"(a0), "r"(a1), "r"(a2), "r"(a3), "r"(b0), "r"(b1));
}

__device__ __forceinline__ uint32_t pack_h2(float lo, float hi) {
    __half2 h = __floats2half2_rn(lo, hi);
    return *reinterpret_cast<uint32_t*>(&h);
}

#define CP_ASYNC16(dst_u32, src_ptr) \
    asm volatile("cp.async.cg.shared.global [%0], [%1], 16;" \
                 :: "r"(dst_u32), "l"(src_ptr) : "memory")
#define CP_COMMIT()  asm volatile("cp.async.commit_group;" ::: "memory")
#define CP_WAIT1()   asm volatile("cp.async.wait_group 1;" ::: "memory")
#define CP_WAIT0()   asm volatile("cp.async.wait_group 0;" ::: "memory")

// ---------------------------------------------------------------------------
// Kernel 1: prep = pack weights (split W^T hi/lo + bias) + split x hi/lo
// ---------------------------------------------------------------------------
#define PACKB ((NQKV * CDIM + 255) / 256)              // 320
#define XB    ((int)((size_t)NROWS * CDIM / 4 / 256))  // 8192

__global__ void prep(const float* __restrict__ x,
                     const float* __restrict__ Wq, const float* __restrict__ Wk,
                     const float* __restrict__ Wv, const float* __restrict__ bq,
                     const float* __restrict__ bk, const float* __restrict__ bv) {
    if (blockIdx.x < PACKB) {
        int i = blockIdx.x * blockDim.x + threadIdx.x;
        if (i < NQKV * CDIM) {
            int n = i >> 8, k = i & 255;
            float w;
            if (n < 32)       w = Wq[k * 32 + n];
            else if (n < 64)  w = Wk[k * 32 + (n - 32)];
            else              w = Wv[k * 256 + (n - 64)];
            __half wh = __float2half_rn(w);
            g_Wth[i] = wh;
            g_Wtl[i] = __float2half_rn(w - __half2float(wh));
        }
        if (i < NQKV)
            g_ball[i] = (i < 32) ? bq[i] : (i < 64 ? bk[i - 32] : bv[i - 64]);
    } else {
        int i = (blockIdx.x - PACKB) * blockDim.x + threadIdx.x;
        if (i >= (int)((size_t)NROWS * CDIM / 4)) return;
        float4 v = ((const float4*)x)[i];
        __half hx = __float2half_rn(v.x), hy = __float2half_rn(v.y);
        __half hz = __float2half_rn(v.z), hw = __float2half_rn(v.w);
        __half2 h01 = __halves2half2(hx, hy);
        __half2 h23 = __halves2half2(hz, hw);
        __half2 l01 = __floats2half2_rn(v.x - __half2float(hx), v.y - __half2float(hy));
        __half2 l23 = __floats2half2_rn(v.z - __half2float(hz), v.w - __half2float(hw));
        ((uint2*)g_x16h)[i] = make_uint2(*(uint32_t*)&h01, *(uint32_t*)&h23);
        ((uint2*)g_x16l)[i] = make_uint2(*(uint32_t*)&l01, *(uint32_t*)&l23);
    }
}

// ---------------------------------------------------------------------------
// Kernel 2: split-fp16 tensor-core GEMM  qkv = x @ W + b
// BM=128, BN=64, K-chunk 32, 256 threads / 8 warps.
// Epilogue: bn0==0 -> q/k written as split fp16; else v written fp16 [tok][c].
// ---------------------------------------------------------------------------
#define GSTRIDE 80
#define GS_AH   0
#define GS_AL   10240
#define GS_BH   20480
#define GS_BL   25600
#define G_STAGE 30720
#define G_SMEM  (2 * G_STAGE)             // 61440

__global__ __launch_bounds__(256) void qkv_gemm_f16() {
    extern __shared__ char gsm[];
    const uint32_t sb = smem_to_u32(gsm);
    const int tid = threadIdx.x, wid = tid >> 5, lane = tid & 31;
    const int bn0 = blockIdx.x * 64;
    const int bm0 = blockIdx.y * 128;
    const int m0 = wid * 16;

    const __half* xh = g_x16h + (size_t)bm0 * CDIM;
    const __half* xl = g_x16l + (size_t)bm0 * CDIM;
    const __half* wth = g_Wth + (size_t)bn0 * CDIM;
    const __half* wtl = g_Wtl + (size_t)bn0 * CDIM;

    {
        const uint32_t S = sb;
#pragma unroll
        for (int t = 0; t < 2; t++) {
            int id = t * 256 + tid; int row = id >> 2, seg = id & 3;
            CP_ASYNC16(S + GS_AH + row * GSTRIDE + seg * 16, xh + (size_t)row * CDIM + seg * 8);
            CP_ASYNC16(S + GS_AL + row * GSTRIDE + seg * 16, xl + (size_t)row * CDIM + seg * 8);
        }
        {
            int row = tid >> 2, seg = tid & 3;
            CP_ASYNC16(S + GS_BH + row * GSTRIDE + seg * 16, wth + (size_t)row * CDIM + seg * 8);
            CP_ASYNC16(S + GS_BL + row * GSTRIDE + seg * 16, wtl + (size_t)row * CDIM + seg * 8);
        }
        CP_COMMIT();
    }

    float D[8][4];
#pragma unroll
    for (int j = 0; j < 8; j++) { D[j][0] = D[j][1] = D[j][2] = D[j][3] = 0.0f; }

    const int g = lane >> 3;
    const uint32_t aOff = (uint32_t)(m0 + ((g & 1) << 3) + (lane & 7)) * GSTRIDE + ((g >> 1) << 4);
    const uint32_t bOff = (uint32_t)(lane & 7) * GSTRIDE + ((lane >> 3) << 4);

    int buf = 0;
    for (int kt = 0; kt < 8; kt++) {
        if (kt < 7) {
            const int k0n = (kt + 1) * 32;
            const uint32_t S = sb + (buf ^ 1) * G_STAGE;
#pragma unroll
            for (int t = 0; t < 2; t++) {
                int id = t * 256 + tid; int row = id >> 2, seg = id & 3;
                CP_ASYNC16(S + GS_AH + row * GSTRIDE + seg * 16,
                           xh + (size_t)row * CDIM + k0n + seg * 8);
                CP_ASYNC16(S + GS_AL + row * GSTRIDE + seg * 16,
                           xl + (size_t)row * CDIM + k0n + seg * 8);
            }
            {
                int row = tid >> 2, seg = tid & 3;
                CP_ASYNC16(S + GS_BH + row * GSTRIDE + seg * 16,
                           wth + (size_t)row * CDIM + k0n + seg * 8);
                CP_ASYNC16(S + GS_BL + row * GSTRIDE + seg * 16,
                           wtl + (size_t)row * CDIM + k0n + seg * 8);
            }
            CP_COMMIT();
            CP_WAIT1();
        } else {
            CP_WAIT0();
        }
        __syncthreads();

        const uint32_t S = sb + buf * G_STAGE;
        uint32_t ah[2][4], al[2][4];
        ldsm4(ah[0][0], ah[0][1], ah[0][2], ah[0][3], S + GS_AH + aOff);
        ldsm4(ah[1][0], ah[1][1], ah[1][2], ah[1][3], S + GS_AH + aOff + 32);
        ldsm4(al[0][0], al[0][1], al[0][2], al[0][3], S + GS_AL + aOff);
        ldsm4(al[1][0], al[1][1], al[1][2], al[1][3], S + GS_AL + aOff + 32);

#pragma unroll
        for (int n8 = 0; n8 < 8; n8++) {
            uint32_t bh0, bh1, bh2, bh3, bl0, bl1, bl2, bl3;
            ldsm4(bh0, bh1, bh2, bh3, S + GS_BH + (uint32_t)(n8 * 8) * GSTRIDE + bOff);
            ldsm4(bl0, bl1, bl2, bl3, S + GS_BL + (uint32_t)(n8 * 8) * GSTRIDE + bOff);
            mma_f16(D[n8], ah[0][0], ah[0][1], ah[0][2], ah[0][3], bh0, bh1);
            mma_f16(D[n8], ah[1][0], ah[1][1], ah[1][2], ah[1][3], bh2, bh3);
            mma_f16(D[n8], ah[0][0], ah[0][1], ah[0][2], ah[0][3], bl0, bl1);
            mma_f16(D[n8], ah[1][0], ah[1][1], ah[1][2], ah[1][3], bl2, bl3);
            mma_f16(D[n8], al[0][0], al[0][1], al[0][2], al[0][3], bh0, bh1);
            mma_f16(D[n8], al[1][0], al[1][1], al[1][2], al[1][3], bh2, bh3);
        }
        __syncthreads();
        buf ^= 1;
    }

    // epilogue
    const int r = bm0 + m0 + (lane >> 2);
    if (bn0 == 0) {
        // q/k: split to fp16 hi/lo, layout [tok][hi32|lo32]
#pragma unroll
        for (int n8 = 0; n8 < 8; n8++) {
            const int col = n8 * 8 + ((lane & 3) << 1);     // 0..62 even
            float b0 = g_ball[col], b1 = g_ball[col + 1];
            __half* dst = (col < 32) ? g_q16 : g_k16;
            const int c = col & 31;
#pragma unroll
            for (int h = 0; h < 2; h++) {
                const int rr = r + h * 8;
                float v0 = D[n8][h * 2 + 0] + b0;
                float v1 = D[n8][h * 2 + 1] + b1;
                __half h0 = __float2half_rn(v0);
                __half h1 = __float2half_rn(v1);
                __half2 hh = __halves2half2(h0, h1);
                *(uint32_t*)&dst[(size_t)rr * 64 + c] = *(uint32_t*)&hh;
                *(uint32_t*)&dst[(size_t)rr * 64 + 32 + c] =
                    pack_h2(v0 - __half2float(h0), v1 - __half2float(h1));
            }
        }
    } else {
        // v: fp16 [tok][c]
#pragma unroll
        for (int n8 = 0; n8 < 8; n8++) {
            const int gc = bn0 + n8 * 8 + ((lane & 3) << 1);
            const int col = gc - 64;
            uint32_t o0 = pack_h2(D[n8][0] + g_ball[gc], D[n8][1] + g_ball[gc + 1]);
            uint32_t o1 = pack_h2(D[n8][2] + g_ball[gc], D[n8][3] + g_ball[gc + 1]);
            *(uint32_t*)&g_v16[(size_t)r * CDIM + col] = o0;
            *(uint32_t*)&g_v16[(size_t)(r + 8) * CDIM + col] = o1;
        }
    }
}

// ---------------------------------------------------------------------------
// Kernel 3: transpose V (fp16) to [b][c][n] fp16
// ---------------------------------------------------------------------------
__global__ void convert_v() {
    __shared__ float tile[32][33];
    const int b = blockIdx.z;
    const int n0 = blockIdx.x * 32, c0 = blockIdx.y * 32;
    const int tx = threadIdx.x, ty = threadIdx.y;   // 32 x 8
#pragma unroll
    for (int i = 0; i < 4; i++) {
        int n = n0 + ty + i * 8;
        tile[ty + i * 8][tx] =
            __half2float(g_v16[((size_t)(b * NTOK + n)) * CDIM + c0 + tx]);
    }
    __syncthreads();
#pragma unroll
    for (int i = 0; i < 4; i++) {
        int c = c0 + ty + i * 8;
        g_vt[((size_t)(b * CDIM + c)) * NTOK + n0 + tx] =
            __float2half_rn(tile[tx][ty + i * 8]);
    }
}

// ---------------------------------------------------------------------------
// Kernel 4: fp16 warp-mma flash attention — R11 structure (champion) with
// 2-term QK: S = (qh+ql)*kh  (K-lo never loaded; K smem halved).
// 256 threads / 8 warps, warp = 16 rows x 256 ch, persistent Q frags,
// warp-local online softmax, 2-stage pipeline, 2 barriers/tile (R11 order).
// ---------------------------------------------------------------------------
#define QSTRIDE 144
#define KSTRIDE 80                          // 64B K-hi data + 16B pad
#define VSTRIDE 144                         // 128B V data + 16B pad
#define SM_Q    0                           // 128*144 = 18432
#define SM_K    18432                       // 2 * 5120
#define K_BUF   5120
#define SM_V    (18432 + 2 * 5120)          // 28672; 2 * 36864
#define V_BUF   36864
#define SM_TOTAL (28672 + 2 * 36864)        // 102400 bytes

__global__ __launch_bounds__(256, 1) void attn_mma(const float* __restrict__ x,
                                                   const float* __restrict__ gamma_p,
                                                   float* __restrict__ out) {
    extern __shared__ char sm[];
    const uint32_t sb = smem_to_u32(sm);
    const int tid = threadIdx.x, wid = tid >> 5, lane = tid & 31;
    const int b = blockIdx.y;
    const int r0 = blockIdx.x * 128;
    const int m0 = wid * 16;

    const __half* qsrc = g_q16 + (size_t)(b * NTOK + r0) * 64;
    const __half* ksrc = g_k16 + (size_t)b * NTOK * 64;
    const __half* vsrc = g_vt + (size_t)b * CDIM * NTOK;

    // ---- load Q tile [128 rows][128B] ----
#pragma unroll
    for (int t = 0; t < 4; t++) {
        int id = t * 256 + tid;
        int row = id >> 3, c = id & 7;
        float4 v = *(const float4*)(qsrc + (size_t)row * 64 + c * 8);
        *(float4*)(sm + SM_Q + row * QSTRIDE + c * 16) = v;
    }

    // ---- prefetch KV tile 0 into buffer 0 ----
    {   // K hi only: 64 rows x 4 chunks = 256 cp
        int row = tid >> 2, seg = tid & 3;
        CP_ASYNC16(sb + SM_K + row * KSTRIDE + seg * 16, ksrc + (size_t)row * 64 + seg * 8);
    }
#pragma unroll
    for (int t = 0; t < 8; t++) {   // V: 256 rows x 8 chunks
        int id = t * 256 + tid; int row = id >> 3, c = id & 7;
        CP_ASYNC16(sb + SM_V + row * VSTRIDE + c * 16, vsrc + (size_t)row * NTOK + c * 8);
    }
    CP_COMMIT();
    __syncthreads();   // Q visible for ldmatrix

    // ---- Q A-fragments (persistent): qa[0,1]=hi dims 0..31, qa[2,3]=lo ----
    uint32_t qa[4][4];
    {
        int g = lane >> 3;
        uint32_t base = sb + SM_Q + (uint32_t)(m0 + ((g & 1) << 3) + (lane & 7)) * QSTRIDE
                        + ((g >> 1) << 4);
#pragma unroll
        for (int kf = 0; kf < 4; kf++)
            ldsm4(qa[kf][0], qa[kf][1], qa[kf][2], qa[kf][3], base + kf * 32);
    }

    const uint32_t bOffK = (uint32_t)(lane & 7) * KSTRIDE + ((lane >> 3) << 4);
    const uint32_t bOffV = (uint32_t)(lane & 7) * VSTRIDE + ((lane >> 3) << 4);

    float D[32][4];
#pragma unroll
    for (int j = 0; j < 32; j++) { D[j][0] = D[j][1] = D[j][2] = D[j][3] = 0.0f; }
    float lsl = 0.0f, lsh = 0.0f;          // running row sums (thread-partial)
    float m_l = -1e30f, m_h = -1e30f;      // running row maxima

    int buf = 0;
    for (int jt = 0; jt < 64; jt++) {
        // R11 order: prefetch next tile into buf^1 (protected by previous
        // iteration's trailing __syncthreads), then wait for current tile.
        if (jt < 63) {
            const int j0n = (jt + 1) * 64;
            const int bn = buf ^ 1;
            {
                int row = tid >> 2, seg = tid & 3;
                CP_ASYNC16(sb + SM_K + bn * K_BUF + row * KSTRIDE + seg * 16,
                           ksrc + (size_t)(j0n + row) * 64 + seg * 8);
            }
#pragma unroll
            for (int t = 0; t < 8; t++) {
                int id = t * 256 + tid; int row = id >> 3, c = id & 7;
                CP_ASYNC16(sb + SM_V + bn * V_BUF + row * VSTRIDE + c * 16,
                           vsrc + (size_t)row * NTOK + j0n + c * 8);
            }
            CP_COMMIT();
            CP_WAIT1();
        } else {
            CP_WAIT0();
        }
        __syncthreads();

        const uint32_t Kb = sb + SM_K + buf * K_BUF;
        const uint32_t Vb = sb + SM_V + buf * V_BUF;

        // ---- QK^T 2-term: S = (qh + ql) * kh ----
        float S[8][4];
#pragma unroll
        for (int j = 0; j < 8; j++) { S[j][0] = S[j][1] = S[j][2] = S[j][3] = 0.0f; }
#pragma unroll
        for (int j = 0; j < 8; j++) {
            uint32_t kh0, kh1, kh2, kh3;
            ldsm4(kh0, kh1, kh2, kh3, Kb + (uint32_t)(j * 8) * KSTRIDE + bOffK);
            mma_f16(S[j], qa[0][0], qa[0][1], qa[0][2], qa[0][3], kh0, kh1);
            mma_f16(S[j], qa[1][0], qa[1][1], qa[1][2], qa[1][3], kh2, kh3);
            mma_f16(S[j], qa[2][0], qa[2][1], qa[2][2], qa[2][3], kh0, kh1);
            mma_f16(S[j], qa[3][0], qa[3][1], qa[3][2], qa[3][3], kh2, kh3);
        }

        // ---- online softmax: tile max -> rescale -> p = exp(s - m_new) ----
        float mtl = -1e30f, mth = -1e30f;
#pragma unroll
        for (int j = 0; j < 8; j++) {
            mtl = fmaxf(mtl, fmaxf(S[j][0], S[j][1]));
            mth = fmaxf(mth, fmaxf(S[j][2], S[j][3]));
        }
        mtl = fmaxf(mtl, __shfl_xor_sync(0xffffffffu, mtl, 1));
        mtl = fmaxf(mtl, __shfl_xor_sync(0xffffffffu, mtl, 2));
        mth = fmaxf(mth, __shfl_xor_sync(0xffffffffu, mth, 1));
        mth = fmaxf(mth, __shfl_xor_sync(0xffffffffu, mth, 2));

        const float mnl = fmaxf(m_l, mtl);
        const float mnh = fmaxf(m_h, mth);
        const float al = __expf(m_l - mnl);
        const float ah = __expf(m_h - mnh);
        m_l = mnl; m_h = mnh;

        uint32_t pha[4][4];
        float psl = 0.0f, psh = 0.0f;
#pragma unroll
        for (int kf = 0; kf < 4; kf++) {
#pragma unroll
            for (int h = 0; h < 2; h++) {
                const int j = 2 * kf + h;
                float p0 = __expf(S[j][0] - mnl);
                float p1 = __expf(S[j][1] - mnl);
                float p2 = __expf(S[j][2] - mnh);
                float p3 = __expf(S[j][3] - mnh);
                psl += p0 + p1;
                psh += p2 + p3;
                pha[kf][h * 2 + 0] = pack_h2(p0, p1);   // row r
                pha[kf][h * 2 + 1] = pack_h2(p2, p3);   // row r+8
            }
        }
        lsl = lsl * al + psl;
        lsh = lsh * ah + psh;

        // rescale accumulators
#pragma unroll
        for (int j2 = 0; j2 < 32; j2++) {
            D[j2][0] *= al; D[j2][1] *= al;
            D[j2][2] *= ah; D[j2][3] *= ah;
        }

        // ---- PV: D += p * v  (single fp16 term) ----
#pragma unroll
        for (int j2 = 0; j2 < 32; j2++) {
            uint32_t v0, v1, v2, v3, v4, v5, v6, v7;
            uint32_t va = Vb + (uint32_t)(j2 * 8) * VSTRIDE + bOffV;
            ldsm4(v0, v1, v2, v3, va);        // keys 0..31
            ldsm4(v4, v5, v6, v7, va + 64);   // keys 32..63
            mma_f16(D[j2], pha[0][0], pha[0][1], pha[0][2], pha[0][3], v0, v1);
            mma_f16(D[j2], pha[1][0], pha[1][1], pha[1][2], pha[1][3], v2, v3);
            mma_f16(D[j2], pha[2][0], pha[2][1], pha[2][2], pha[2][3], v4, v5);
            mma_f16(D[j2], pha[3][0], pha[3][1], pha[3][2], pha[3][3], v6, v7);
        }

        __syncthreads();   // compute done before this buffer is overwritten
        buf ^= 1;
    }

    // ---- row sums (quad reduction) + epilogue: out = gamma * D / l + x ----
    lsl += __shfl_xor_sync(0xffffffffu, lsl, 1);
    lsl += __shfl_xor_sync(0xffffffffu, lsl, 2);
    lsh += __shfl_xor_sync(0xffffffffu, lsh, 1);
    lsh += __shfl_xor_sync(0xffffffffu, lsh, 2);

    const float g = *gamma_p;
    const float il = g / lsl;
    const float ih = g / lsh;
    const int r = r0 + m0 + (lane >> 2);
    const size_t base_lo = ((size_t)(b * NTOK) + r) * CDIM;
    const size_t base_hi = base_lo + 8 * CDIM;
#pragma unroll
    for (int j2 = 0; j2 < 32; j2++) {
        const int col = j2 * 8 + ((lane & 3) << 1);
        float2 xv = *(const float2*)(x + base_lo + col);
        float2 o;
        o.x = D[j2][0] * il + xv.x;
        o.y = D[j2][1] * il + xv.y;
        *(float2*)(out + base_lo + col) = o;
        float2 xw = *(const float2*)(x + base_hi + col);
        float2 o2;
        o2.x = D[j2][2] * ih + xw.x;
        o2.y = D[j2][3] * ih + xw.y;
        *(float2*)(out + base_hi + col) = o2;
    }
}

// ---------------------------------------------------------------------------
extern "C" void kernel_launch(void* const* d_in, const int* in_sizes, int n_in,
                              void* d_out, int out_size) {
    const float* x     = (const float*)d_in[0];
    const float* Wq    = (const float*)d_in[1];
    const float* bq    = (const float*)d_in[2];
    const float* Wk    = (const float*)d_in[3];
    const float* bk    = (const float*)d_in[4];
    const float* Wv    = (const float*)d_in[5];
    const float* bv    = (const float*)d_in[6];
    const float* gamma = (const float*)d_in[7];
    float* out = (float*)d_out;

    prep<<<PACKB + XB, 256>>>(x, Wq, Wk, Wv, bq, bk, bv);

    cudaFuncSetAttribute(qkv_gemm_f16, cudaFuncAttributeMaxDynamicSharedMemorySize, G_SMEM);
    qkv_gemm_f16<<<dim3(NQKV / 64, NROWS / 128), 256, G_SMEM>>>();

    convert_v<<<dim3(NTOK / 32, CDIM / 32, BATCH), dim3(32, 8)>>>();

    cudaFuncSetAttribute(attn_mma, cudaFuncAttributeMaxDynamicSharedMemorySize, SM_TOTAL);
    attn_mma<<<dim3(NTOK / 128, BATCH), 256, SM_TOTAL>>>(x, gamma, out);
}